// round 1
// baseline (speedup 1.0000x reference)
#include <cuda_runtime.h>
#include <math.h>

#define D_MODEL 1024
#define N_HEADS 16
#define HEAD_DIM 64
#define BATCH 4
#define SEQ 2048
#define BT (BATCH * SEQ)          // 8192 rows
#define QKV_N (3 * D_MODEL)       // 3072

// Scratch (allocations are forbidden; device globals are the sanctioned path)
__device__ float g_qkv[(size_t)BT * QKV_N];     // ~100.7 MB
__device__ float g_attn[(size_t)BT * D_MODEL];  // ~33.6 MB

// ----------------------------------------------------------------------------
// GEMM: C[M,N] = A[M,K] @ W[N,K]^T + bias[N]
// 64x64 block tile, BK=16, 256 threads, 4x4 register tile per thread.
// ----------------------------------------------------------------------------
template <int BM, int BN, int BK>
__global__ void gemm_bias_kernel(const float* __restrict__ A,
                                 const float* __restrict__ W,
                                 const float* __restrict__ bias,
                                 float* __restrict__ C,
                                 int M, int N, int K) {
    __shared__ float As[BM][BK];       // [row][k]
    __shared__ float WsT[BK][BN];      // [k][col]  (transposed on store)

    const int tid = threadIdx.x;       // 256 threads
    const int tx = tid & 15;           // 0..15 -> col group
    const int ty = tid >> 4;           // 0..15 -> row group
    const int row0 = blockIdx.y * BM;
    const int col0 = blockIdx.x * BN;

    // load mapping: each thread loads one float4 of A-tile and one of W-tile
    const int l_r = tid >> 2;          // 0..63
    const int l_c = (tid & 3) << 2;    // 0,4,8,12

    float acc[4][4] = {};

    for (int k0 = 0; k0 < K; k0 += BK) {
        float4 av = *(const float4*)(A + (size_t)(row0 + l_r) * K + k0 + l_c);
        float4 wv = *(const float4*)(W + (size_t)(col0 + l_r) * K + k0 + l_c);
        __syncthreads();   // protect prior iteration's smem reads
        *(float4*)&As[l_r][l_c] = av;
        WsT[l_c + 0][l_r] = wv.x;
        WsT[l_c + 1][l_r] = wv.y;
        WsT[l_c + 2][l_r] = wv.z;
        WsT[l_c + 3][l_r] = wv.w;
        __syncthreads();

        #pragma unroll
        for (int kk = 0; kk < BK; kk++) {
            float breg[4];
            *(float4*)breg = *(const float4*)&WsT[kk][tx << 2];
            #pragma unroll
            for (int a = 0; a < 4; a++) {
                float av2 = As[(ty << 2) + a][kk];
                acc[a][0] += av2 * breg[0];
                acc[a][1] += av2 * breg[1];
                acc[a][2] += av2 * breg[2];
                acc[a][3] += av2 * breg[3];
            }
        }
    }

    float4 bv = *(const float4*)(bias + col0 + (tx << 2));
    #pragma unroll
    for (int a = 0; a < 4; a++) {
        float4 o;
        o.x = acc[a][0] + bv.x;
        o.y = acc[a][1] + bv.y;
        o.z = acc[a][2] + bv.z;
        o.w = acc[a][3] + bv.w;
        *(float4*)(C + (size_t)(row0 + (ty << 2) + a) * N + col0 + (tx << 2)) = o;
    }
}

// ----------------------------------------------------------------------------
// Flash-style attention.
// qkv layout per reference: row (b,t), head h: q at cols [h*192, h*192+64),
// k at [h*192+64, h*192+128), v at [h*192+128, h*192+192).
// One CTA = one (b,h) pair x 64 query rows. 256 threads, 4x4 reg tile.
// Smem: Qs (natural), KVs (K transposed [d][key], then reused for V [key][d]),
// Ps (probabilities). 3 * 16 KB = 48 KB static.
// ----------------------------------------------------------------------------
__global__ void attn_kernel(const float* __restrict__ qkv,
                            float* __restrict__ out) {
    __shared__ float Qs[64][64];   // [qrow][d]
    __shared__ float KVs[64][64];  // phase K: [d][key] ; phase V: [key][d]
    __shared__ float Ps[64][64];   // [qrow][key]

    const int tid = threadIdx.x;
    const int tx = tid & 15;
    const int ty = tid >> 4;
    const int bh = blockIdx.y;
    const int bb = bh >> 4;        // batch
    const int h = bh & 15;         // head
    const int q0 = blockIdx.x * 64;
    const float scale = 0.125f;    // 1/sqrt(64)

    const size_t rowstride = QKV_N;
    const size_t base = (size_t)bb * SEQ * rowstride + (size_t)h * (3 * HEAD_DIM);

    // ---- load Q tile (coalesced float4 along d) ----
    {
        #pragma unroll
        for (int i = 0; i < 4; i++) {
            int f = tid + i * 256;       // 0..1023 float4s
            int r = f >> 4;              // qrow 0..63
            int d = (f & 15) << 2;       // 0..60
            float4 v = *(const float4*)(qkv + base + (size_t)(q0 + r) * rowstride + d);
            *(float4*)&Qs[r][d] = v;
        }
    }

    float m[4], l[4], o[4][4];
    #pragma unroll
    for (int a = 0; a < 4; a++) {
        m[a] = -1e30f; l[a] = 0.f;
        o[a][0] = o[a][1] = o[a][2] = o[a][3] = 0.f;
    }

    for (int kt = 0; kt < SEQ / 64; kt++) {
        const int k0 = kt * 64;

        // ---- load K tile transposed: KVs[d][key] ----
        __syncthreads();  // prior V reads done; Q store visible (first iter)
        #pragma unroll
        for (int i = 0; i < 4; i++) {
            int f = tid + i * 256;
            int r = f >> 4;              // key row within tile
            int d = (f & 15) << 2;
            float4 v = *(const float4*)(qkv + base + (size_t)(k0 + r) * rowstride + HEAD_DIM + d);
            KVs[d + 0][r] = v.x;
            KVs[d + 1][r] = v.y;
            KVs[d + 2][r] = v.z;
            KVs[d + 3][r] = v.w;
        }
        __syncthreads();

        // ---- S = Q @ K^T (register 4x4) ----
        float s[4][4] = {};
        #pragma unroll
        for (int kk = 0; kk < 64; kk++) {
            float kreg[4];
            *(float4*)kreg = *(const float4*)&KVs[kk][tx << 2];
            #pragma unroll
            for (int a = 0; a < 4; a++) {
                float qv = Qs[(ty << 2) + a][kk];
                s[a][0] += qv * kreg[0];
                s[a][1] += qv * kreg[1];
                s[a][2] += qv * kreg[2];
                s[a][3] += qv * kreg[3];
            }
        }

        // ---- online softmax ----
        #pragma unroll
        for (int a = 0; a < 4; a++) {
            s[a][0] *= scale; s[a][1] *= scale; s[a][2] *= scale; s[a][3] *= scale;
            float mt = fmaxf(fmaxf(s[a][0], s[a][1]), fmaxf(s[a][2], s[a][3]));
            #pragma unroll
            for (int off = 8; off > 0; off >>= 1)
                mt = fmaxf(mt, __shfl_xor_sync(0xffffffffu, mt, off));
            float mnew = fmaxf(m[a], mt);
            float alpha = __expf(m[a] - mnew);
            float p0 = __expf(s[a][0] - mnew);
            float p1 = __expf(s[a][1] - mnew);
            float p2 = __expf(s[a][2] - mnew);
            float p3 = __expf(s[a][3] - mnew);
            float rs = p0 + p1 + p2 + p3;
            #pragma unroll
            for (int off = 8; off > 0; off >>= 1)
                rs += __shfl_xor_sync(0xffffffffu, rs, off);
            l[a] = l[a] * alpha + rs;
            m[a] = mnew;
            o[a][0] *= alpha; o[a][1] *= alpha; o[a][2] *= alpha; o[a][3] *= alpha;
            float4 pv = make_float4(p0, p1, p2, p3);
            *(float4*)&Ps[(ty << 2) + a][tx << 2] = pv;
        }
        __syncthreads();  // S-compute reads of KVs(K) done; Ps written

        // ---- load V tile natural layout: KVs[key][d] ----
        #pragma unroll
        for (int i = 0; i < 4; i++) {
            int f = tid + i * 256;
            int r = f >> 4;
            int d = (f & 15) << 2;
            float4 v = *(const float4*)(qkv + base + (size_t)(k0 + r) * rowstride + 2 * HEAD_DIM + d);
            *(float4*)&KVs[r][d] = v;
        }
        __syncthreads();

        // ---- O += P @ V ----
        #pragma unroll
        for (int kk = 0; kk < 64; kk++) {
            float vreg[4];
            *(float4*)vreg = *(const float4*)&KVs[kk][tx << 2];
            #pragma unroll
            for (int a = 0; a < 4; a++) {
                float pv = Ps[(ty << 2) + a][kk];
                o[a][0] += pv * vreg[0];
                o[a][1] += pv * vreg[1];
                o[a][2] += pv * vreg[2];
                o[a][3] += pv * vreg[3];
            }
        }
    }

    // ---- normalize and store: out[(bb*SEQ + q)*D_MODEL + h*64 + c] ----
    #pragma unroll
    for (int a = 0; a < 4; a++) {
        float inv = 1.0f / l[a];
        float4 ov;
        ov.x = o[a][0] * inv;
        ov.y = o[a][1] * inv;
        ov.z = o[a][2] * inv;
        ov.w = o[a][3] * inv;
        size_t orow = (size_t)bb * SEQ + q0 + (ty << 2) + a;
        *(float4*)(out + orow * D_MODEL + h * HEAD_DIM + (tx << 2)) = ov;
    }
}

// ----------------------------------------------------------------------------
extern "C" void kernel_launch(void* const* d_in, const int* in_sizes, int n_in,
                              void* d_out, int out_size) {
    // Defensive input mapping by element count (dict order: x, Wqkv, bqkv, Wo, bo)
    const float* x = nullptr;
    const float* Wqkv = nullptr;
    const float* bqkv = nullptr;
    const float* Wo = nullptr;
    const float* bo = nullptr;
    for (int i = 0; i < n_in; i++) {
        int s = in_sizes[i];
        const float* p = (const float*)d_in[i];
        if (s == BT * D_MODEL) x = p;
        else if (s == 3 * D_MODEL * D_MODEL) Wqkv = p;
        else if (s == 3 * D_MODEL) bqkv = p;
        else if (s == D_MODEL * D_MODEL) Wo = p;
        else if (s == D_MODEL) bo = p;
    }

    float* qkv = nullptr;
    float* attn = nullptr;
    cudaGetSymbolAddress((void**)&qkv, g_qkv);
    cudaGetSymbolAddress((void**)&attn, g_attn);

    dim3 blk(256);

    // 1) QKV projection: [8192,1024] @ [3072,1024]^T + bqkv -> [8192,3072]
    gemm_bias_kernel<64, 64, 16>
        <<<dim3(QKV_N / 64, BT / 64), blk>>>(x, Wqkv, bqkv, qkv, BT, QKV_N, D_MODEL);

    // 2) attention -> [B,T,C] layout directly
    attn_kernel<<<dim3(SEQ / 64, BATCH * N_HEADS), blk>>>(qkv, attn);

    // 3) output projection: [8192,1024] @ [1024,1024]^T + bo -> d_out
    gemm_bias_kernel<64, 64, 16>
        <<<dim3(D_MODEL / 64, BT / 64), blk>>>(attn, Wo, bo, (float*)d_out, BT, D_MODEL, D_MODEL);
}

// round 3
// speedup vs baseline: 1.5226x; 1.5226x over previous
#include <cuda_runtime.h>
#include <cuda_bf16.h>
#include <cstdint>
#include <math.h>

#define D_MODEL 1024
#define N_HEADS 16
#define HEAD_DIM 64
#define BATCH 4
#define SEQ 2048
#define BT (BATCH * SEQ)          // 8192 rows
#define QKV_N (3 * D_MODEL)       // 3072

// ---------------- scratch (device globals; allocation is forbidden) ---------
__device__ float g_qkv[(size_t)BT * QKV_N];
__device__ float g_attn[(size_t)BT * D_MODEL];
__device__ __nv_bfloat16 g_ahi[(size_t)BT * D_MODEL];
__device__ __nv_bfloat16 g_alo[(size_t)BT * D_MODEL];
__device__ __nv_bfloat16 g_wqkv_hi[(size_t)QKV_N * D_MODEL];
__device__ __nv_bfloat16 g_wqkv_lo[(size_t)QKV_N * D_MODEL];
__device__ __nv_bfloat16 g_wo_hi[(size_t)D_MODEL * D_MODEL];
__device__ __nv_bfloat16 g_wo_lo[(size_t)D_MODEL * D_MODEL];

// ---------------- helpers ----------------------------------------------------
__device__ __forceinline__ uint32_t smem_to_u32(const void* p) {
    uint32_t a;
    asm("{ .reg .u64 t; cvta.to.shared.u64 t, %1; cvt.u32.u64 %0, t; }" : "=r"(a) : "l"(p));
    return a;
}
#define SWZ(off) ((off) ^ (((off) >> 3) & 0x70))

__device__ __forceinline__ void ldsm_x4(uint32_t addr, uint32_t& r0, uint32_t& r1,
                                        uint32_t& r2, uint32_t& r3) {
    asm volatile("ldmatrix.sync.aligned.m8n8.x4.shared.b16 {%0,%1,%2,%3}, [%4];"
                 : "=r"(r0), "=r"(r1), "=r"(r2), "=r"(r3) : "r"(addr));
}

__device__ __forceinline__ void mma16816(float* d, const uint32_t* a, const uint32_t* b) {
    asm volatile(
        "mma.sync.aligned.m16n8k16.row.col.f32.bf16.bf16.f32 "
        "{%0,%1,%2,%3}, {%4,%5,%6,%7}, {%8,%9}, {%0,%1,%2,%3};"
        : "+f"(d[0]), "+f"(d[1]), "+f"(d[2]), "+f"(d[3])
        : "r"(a[0]), "r"(a[1]), "r"(a[2]), "r"(a[3]), "r"(b[0]), "r"(b[1]));
}

__device__ __forceinline__ void cp_async16(uint32_t dst, const void* src) {
    asm volatile("cp.async.cg.shared.global [%0], [%1], 16;" :: "r"(dst), "l"(src));
}
#define CP_COMMIT() asm volatile("cp.async.commit_group;" ::: "memory")

// ---------------- split fp32 -> (bf16 hi, bf16 lo) ---------------------------
__global__ void split_bf16_kernel(const float* __restrict__ in,
                                  __nv_bfloat16* __restrict__ hi,
                                  __nv_bfloat16* __restrict__ lo, int n4) {
    int i = blockIdx.x * blockDim.x + threadIdx.x;
    if (i >= n4) return;
    float4 v = ((const float4*)in)[i];
    __nv_bfloat16 h0 = __float2bfloat16_rn(v.x);
    __nv_bfloat16 h1 = __float2bfloat16_rn(v.y);
    __nv_bfloat16 h2 = __float2bfloat16_rn(v.z);
    __nv_bfloat16 h3 = __float2bfloat16_rn(v.w);
    __nv_bfloat16 l0 = __float2bfloat16_rn(v.x - __bfloat162float(h0));
    __nv_bfloat16 l1 = __float2bfloat16_rn(v.y - __bfloat162float(h1));
    __nv_bfloat16 l2 = __float2bfloat16_rn(v.z - __bfloat162float(h2));
    __nv_bfloat16 l3 = __float2bfloat16_rn(v.w - __bfloat162float(h3));
    ((__nv_bfloat162*)hi)[2 * i]     = __nv_bfloat162(h0, h1);
    ((__nv_bfloat162*)hi)[2 * i + 1] = __nv_bfloat162(h2, h3);
    ((__nv_bfloat162*)lo)[2 * i]     = __nv_bfloat162(l0, l1);
    ((__nv_bfloat162*)lo)[2 * i + 1] = __nv_bfloat162(l2, l3);
}

// ---------------- HMMA GEMM ---------------------------------------------------
// C[M,N] = Ahi@Bhi^T + Ahi@Blo^T + Alo@Bhi^T + bias.  A:[M,K], B:[N,K] bf16.
// CTA tile 128x128, BK=64, double-buffered cp.async, 8 warps (2x4), warp 64x32.
#define GEMM_KC 64
#define TILE_B 16384                       // one 128x64 bf16 tile
#define STAGE_B (4 * TILE_B)               // Ahi, Alo, Bhi, Blo
#define GEMM_SMEM (2 * STAGE_B)            // 131072

__device__ __forceinline__ void load_tile_async(uint32_t smem_dst,
                                                const __nv_bfloat16* __restrict__ g,
                                                int base_row, int K, int kc, int tid) {
    #pragma unroll
    for (int i = 0; i < 4; i++) {
        int idx = tid + i * 256;
        int r = idx >> 3;
        int c = (idx & 7) << 4;            // 16B chunk byte offset
        const char* src = (const char*)(g + (size_t)(base_row + r) * K + kc) + c;
        cp_async16(smem_dst + SWZ((uint32_t)(r * 128 + c)), src);
    }
}

__global__ void __launch_bounds__(256, 1)
gemm_tc_kernel(const __nv_bfloat16* __restrict__ Ahi,
               const __nv_bfloat16* __restrict__ Alo,
               const __nv_bfloat16* __restrict__ Bhi,
               const __nv_bfloat16* __restrict__ Blo,
               const float* __restrict__ bias,
               float* __restrict__ C,
               int M, int N, int K) {
    extern __shared__ char smem[];
    const uint32_t sb = smem_to_u32(smem);
    const int tid = threadIdx.x;
    const int wid = tid >> 5;
    const int lane = tid & 31;
    const int warp_m = wid >> 2;           // 0..1 -> 64 rows each
    const int warp_n = wid & 3;            // 0..3 -> 32 cols each
    const int row0 = blockIdx.y * 128;
    const int col0 = blockIdx.x * 128;
    const int NC = K / GEMM_KC;

    float acc[4][4][4];                    // [mtile][ntile][frag]
    #pragma unroll
    for (int mt = 0; mt < 4; mt++)
        #pragma unroll
        for (int nt = 0; nt < 4; nt++)
            acc[mt][nt][0] = acc[mt][nt][1] = acc[mt][nt][2] = acc[mt][nt][3] = 0.f;

    // lane-invariant parts of ldmatrix addresses (byte offsets before swizzle)
    const uint32_t a_row = warp_m * 64 + (lane & 15);
    const uint32_t a_colb = (lane >> 4) << 4;            // 0 or 16
    const uint32_t b_row = warp_n * 32 + (lane & 7) + ((lane >> 4) & 1) * 8;
    const uint32_t b_colb = ((lane >> 3) & 1) << 4;      // 0 or 16

    // prologue
    {
        uint32_t s0 = sb;
        load_tile_async(s0,              Ahi, row0, K, 0, tid);
        load_tile_async(s0 + TILE_B,     Alo, row0, K, 0, tid);
        load_tile_async(s0 + 2 * TILE_B, Bhi, col0, K, 0, tid);
        load_tile_async(s0 + 3 * TILE_B, Blo, col0, K, 0, tid);
        CP_COMMIT();
    }

    for (int c = 0; c < NC; ++c) {
        if (c + 1 < NC) {
            uint32_t sn = sb + ((c + 1) & 1) * STAGE_B;
            int kc = (c + 1) * GEMM_KC;
            load_tile_async(sn,              Ahi, row0, K, kc, tid);
            load_tile_async(sn + TILE_B,     Alo, row0, K, kc, tid);
            load_tile_async(sn + 2 * TILE_B, Bhi, col0, K, kc, tid);
            load_tile_async(sn + 3 * TILE_B, Blo, col0, K, kc, tid);
            CP_COMMIT();
            asm volatile("cp.async.wait_group 1;" ::: "memory");
        } else {
            asm volatile("cp.async.wait_group 0;" ::: "memory");
        }
        __syncthreads();

        const uint32_t s = sb + (c & 1) * STAGE_B;
        #pragma unroll
        for (int ks = 0; ks < 4; ks++) {
            const uint32_t kb = ks * 32;   // byte offset of this k16 within the 128B row
            uint32_t aH[4][4], aL[4][4], bH[4][2], bL[4][2];
            #pragma unroll
            for (int mt = 0; mt < 4; mt++) {
                uint32_t off = SWZ((a_row + mt * 16) * 128 + kb + a_colb);
                ldsm_x4(s + off,          aH[mt][0], aH[mt][1], aH[mt][2], aH[mt][3]);
                ldsm_x4(s + TILE_B + off, aL[mt][0], aL[mt][1], aL[mt][2], aL[mt][3]);
            }
            #pragma unroll
            for (int np = 0; np < 2; np++) {
                uint32_t off = SWZ((b_row + np * 16) * 128 + kb + b_colb);
                uint32_t r0, r1, r2, r3;
                ldsm_x4(s + 2 * TILE_B + off, r0, r1, r2, r3);
                bH[np * 2][0] = r0; bH[np * 2][1] = r1;
                bH[np * 2 + 1][0] = r2; bH[np * 2 + 1][1] = r3;
                ldsm_x4(s + 3 * TILE_B + off, r0, r1, r2, r3);
                bL[np * 2][0] = r0; bL[np * 2][1] = r1;
                bL[np * 2 + 1][0] = r2; bL[np * 2 + 1][1] = r3;
            }
            #pragma unroll
            for (int mt = 0; mt < 4; mt++)
                #pragma unroll
                for (int nt = 0; nt < 4; nt++) {
                    mma16816(acc[mt][nt], aH[mt], bH[nt]);
                    mma16816(acc[mt][nt], aH[mt], bL[nt]);
                    mma16816(acc[mt][nt], aL[mt], bH[nt]);
                }
        }
        __syncthreads();
    }

    // epilogue: c-frag lane mapping: rows l>>2 and (l>>2)+8, cols (l&3)*2, +1
    const int er0 = row0 + warp_m * 64 + (lane >> 2);
    const int ec0 = col0 + warp_n * 32 + (lane & 3) * 2;
    #pragma unroll
    for (int mt = 0; mt < 4; mt++) {
        #pragma unroll
        for (int nt = 0; nt < 4; nt++) {
            const int cc = ec0 + nt * 8;
            const float b0 = bias[cc], b1 = bias[cc + 1];
            const int r0 = er0 + mt * 16;
            float2 v0 = make_float2(acc[mt][nt][0] + b0, acc[mt][nt][1] + b1);
            float2 v1 = make_float2(acc[mt][nt][2] + b0, acc[mt][nt][3] + b1);
            *(float2*)(C + (size_t)r0 * N + cc) = v0;
            *(float2*)(C + (size_t)(r0 + 8) * N + cc) = v1;
        }
    }
}

// ---------------- SIMT flash attention (unchanged, known-correct) ------------
__global__ void attn_kernel(const float* __restrict__ qkv,
                            float* __restrict__ out) {
    __shared__ float Qs[64][64];
    __shared__ float KVs[64][64];
    __shared__ float Ps[64][64];

    const int tid = threadIdx.x;
    const int tx = tid & 15;
    const int ty = tid >> 4;
    const int bh = blockIdx.y;
    const int bb = bh >> 4;
    const int h = bh & 15;
    const int q0 = blockIdx.x * 64;
    const float scale = 0.125f;

    const size_t rowstride = QKV_N;
    const size_t base = (size_t)bb * SEQ * rowstride + (size_t)h * (3 * HEAD_DIM);

    #pragma unroll
    for (int i = 0; i < 4; i++) {
        int f = tid + i * 256;
        int r = f >> 4;
        int d = (f & 15) << 2;
        float4 v = *(const float4*)(qkv + base + (size_t)(q0 + r) * rowstride + d);
        *(float4*)&Qs[r][d] = v;
    }

    float m[4], l[4], o[4][4];
    #pragma unroll
    for (int a = 0; a < 4; a++) {
        m[a] = -1e30f; l[a] = 0.f;
        o[a][0] = o[a][1] = o[a][2] = o[a][3] = 0.f;
    }

    for (int kt = 0; kt < SEQ / 64; kt++) {
        const int k0 = kt * 64;

        __syncthreads();
        #pragma unroll
        for (int i = 0; i < 4; i++) {
            int f = tid + i * 256;
            int r = f >> 4;
            int d = (f & 15) << 2;
            float4 v = *(const float4*)(qkv + base + (size_t)(k0 + r) * rowstride + HEAD_DIM + d);
            KVs[d + 0][r] = v.x;
            KVs[d + 1][r] = v.y;
            KVs[d + 2][r] = v.z;
            KVs[d + 3][r] = v.w;
        }
        __syncthreads();

        float s[4][4] = {};
        #pragma unroll
        for (int kk = 0; kk < 64; kk++) {
            float kreg[4];
            *(float4*)kreg = *(const float4*)&KVs[kk][tx << 2];
            #pragma unroll
            for (int a = 0; a < 4; a++) {
                float qv = Qs[(ty << 2) + a][kk];
                s[a][0] += qv * kreg[0];
                s[a][1] += qv * kreg[1];
                s[a][2] += qv * kreg[2];
                s[a][3] += qv * kreg[3];
            }
        }

        #pragma unroll
        for (int a = 0; a < 4; a++) {
            s[a][0] *= scale; s[a][1] *= scale; s[a][2] *= scale; s[a][3] *= scale;
            float mt = fmaxf(fmaxf(s[a][0], s[a][1]), fmaxf(s[a][2], s[a][3]));
            #pragma unroll
            for (int off = 8; off > 0; off >>= 1)
                mt = fmaxf(mt, __shfl_xor_sync(0xffffffffu, mt, off));
            float mnew = fmaxf(m[a], mt);
            float alpha = __expf(m[a] - mnew);
            float p0 = __expf(s[a][0] - mnew);
            float p1 = __expf(s[a][1] - mnew);
            float p2 = __expf(s[a][2] - mnew);
            float p3 = __expf(s[a][3] - mnew);
            float rs = p0 + p1 + p2 + p3;
            #pragma unroll
            for (int off = 8; off > 0; off >>= 1)
                rs += __shfl_xor_sync(0xffffffffu, rs, off);
            l[a] = l[a] * alpha + rs;
            m[a] = mnew;
            o[a][0] *= alpha; o[a][1] *= alpha; o[a][2] *= alpha; o[a][3] *= alpha;
            float4 pv = make_float4(p0, p1, p2, p3);
            *(float4*)&Ps[(ty << 2) + a][tx << 2] = pv;
        }
        __syncthreads();

        #pragma unroll
        for (int i = 0; i < 4; i++) {
            int f = tid + i * 256;
            int r = f >> 4;
            int d = (f & 15) << 2;
            float4 v = *(const float4*)(qkv + base + (size_t)(k0 + r) * rowstride + 2 * HEAD_DIM + d);
            *(float4*)&KVs[r][d] = v;
        }
        __syncthreads();

        #pragma unroll
        for (int kk = 0; kk < 64; kk++) {
            float vreg[4];
            *(float4*)vreg = *(const float4*)&KVs[kk][tx << 2];
            #pragma unroll
            for (int a = 0; a < 4; a++) {
                float pv = Ps[(ty << 2) + a][kk];
                o[a][0] += pv * vreg[0];
                o[a][1] += pv * vreg[1];
                o[a][2] += pv * vreg[2];
                o[a][3] += pv * vreg[3];
            }
        }
    }

    #pragma unroll
    for (int a = 0; a < 4; a++) {
        float inv = 1.0f / l[a];
        float4 ov;
        ov.x = o[a][0] * inv;
        ov.y = o[a][1] * inv;
        ov.z = o[a][2] * inv;
        ov.w = o[a][3] * inv;
        size_t orow = (size_t)bb * SEQ + q0 + (ty << 2) + a;
        *(float4*)(out + orow * D_MODEL + h * HEAD_DIM + (tx << 2)) = ov;
    }
}

// -----------------------------------------------------------------------------
extern "C" void kernel_launch(void* const* d_in, const int* in_sizes, int n_in,
                              void* d_out, int out_size) {
    const float* x = nullptr;
    const float* Wqkv = nullptr;
    const float* bqkv = nullptr;
    const float* Wo = nullptr;
    const float* bo = nullptr;
    for (int i = 0; i < n_in; i++) {
        int s = in_sizes[i];
        const float* p = (const float*)d_in[i];
        if (s == BT * D_MODEL) x = p;
        else if (s == 3 * D_MODEL * D_MODEL) Wqkv = p;
        else if (s == 3 * D_MODEL) bqkv = p;
        else if (s == D_MODEL * D_MODEL) Wo = p;
        else if (s == D_MODEL) bo = p;
    }

    float* qkv = nullptr;  float* attn = nullptr;
    __nv_bfloat16 *ahi, *alo, *wqhi, *wqlo, *wohi, *wolo;
    cudaGetSymbolAddress((void**)&qkv, g_qkv);
    cudaGetSymbolAddress((void**)&attn, g_attn);
    cudaGetSymbolAddress((void**)&ahi, g_ahi);
    cudaGetSymbolAddress((void**)&alo, g_alo);
    cudaGetSymbolAddress((void**)&wqhi, g_wqkv_hi);
    cudaGetSymbolAddress((void**)&wqlo, g_wqkv_lo);
    cudaGetSymbolAddress((void**)&wohi, g_wo_hi);
    cudaGetSymbolAddress((void**)&wolo, g_wo_lo);

    static bool attr_done = false;
    if (!attr_done) {
        cudaFuncSetAttribute(gemm_tc_kernel,
                             cudaFuncAttributeMaxDynamicSharedMemorySize, GEMM_SMEM);
        attr_done = true;
    }

    // split inputs to bf16 hi/lo
    {
        int n4 = BT * D_MODEL / 4;
        split_bf16_kernel<<<(n4 + 255) / 256, 256>>>(x, ahi, alo, n4);
        n4 = QKV_N * D_MODEL / 4;
        split_bf16_kernel<<<(n4 + 255) / 256, 256>>>(Wqkv, wqhi, wqlo, n4);
        n4 = D_MODEL * D_MODEL / 4;
        split_bf16_kernel<<<(n4 + 255) / 256, 256>>>(Wo, wohi, wolo, n4);
    }

    // 1) QKV projection (HMMA)
    gemm_tc_kernel<<<dim3(QKV_N / 128, BT / 128), 256, GEMM_SMEM>>>(
        ahi, alo, wqhi, wqlo, bqkv, qkv, BT, QKV_N, D_MODEL);

    // 2) attention (SIMT, unchanged)
    attn_kernel<<<dim3(SEQ / 64, BATCH * N_HEADS), 256>>>(qkv, attn);

    // 3) split attention output, then output projection (HMMA)
    {
        int n4 = BT * D_MODEL / 4;
        split_bf16_kernel<<<(n4 + 255) / 256, 256>>>(attn, ahi, alo, n4);
    }
    gemm_tc_kernel<<<dim3(D_MODEL / 128, BT / 128), 256, GEMM_SMEM>>>(
        ahi, alo, wohi, wolo, bo, (float*)d_out, BT, D_MODEL, D_MODEL);
}

// round 4
// speedup vs baseline: 3.7402x; 2.4565x over previous
#include <cuda_runtime.h>
#include <cuda_bf16.h>
#include <cstdint>
#include <math.h>

#define D_MODEL 1024
#define N_HEADS 16
#define HEAD_DIM 64
#define BATCH 4
#define SEQ 2048
#define BT (BATCH * SEQ)          // 8192 rows
#define QKV_N (3 * D_MODEL)       // 3072

// ---------------- scratch (device globals; allocation is forbidden) ---------
__device__ float g_qkv[(size_t)BT * QKV_N];
__device__ __nv_bfloat16 g_ahi[(size_t)BT * D_MODEL];
__device__ __nv_bfloat16 g_alo[(size_t)BT * D_MODEL];
__device__ __nv_bfloat16 g_wqkv_hi[(size_t)QKV_N * D_MODEL];
__device__ __nv_bfloat16 g_wqkv_lo[(size_t)QKV_N * D_MODEL];
__device__ __nv_bfloat16 g_wo_hi[(size_t)D_MODEL * D_MODEL];
__device__ __nv_bfloat16 g_wo_lo[(size_t)D_MODEL * D_MODEL];
// per-head Q/K/V bf16 hi/lo: [B*H][T][64]
__device__ __nv_bfloat16 g_qh[(size_t)BT * D_MODEL];
__device__ __nv_bfloat16 g_ql[(size_t)BT * D_MODEL];
__device__ __nv_bfloat16 g_kh[(size_t)BT * D_MODEL];
__device__ __nv_bfloat16 g_kl[(size_t)BT * D_MODEL];
__device__ __nv_bfloat16 g_vh[(size_t)BT * D_MODEL];
__device__ __nv_bfloat16 g_vl[(size_t)BT * D_MODEL];

// ---------------- helpers ----------------------------------------------------
__device__ __forceinline__ uint32_t smem_to_u32(const void* p) {
    uint32_t a;
    asm("{ .reg .u64 t; cvta.to.shared.u64 t, %1; cvt.u32.u64 %0, t; }" : "=r"(a) : "l"(p));
    return a;
}
#define SWZ(off) ((off) ^ (((off) >> 3) & 0x70))

__device__ __forceinline__ void ldsm_x4(uint32_t addr, uint32_t& r0, uint32_t& r1,
                                        uint32_t& r2, uint32_t& r3) {
    asm volatile("ldmatrix.sync.aligned.m8n8.x4.shared.b16 {%0,%1,%2,%3}, [%4];"
                 : "=r"(r0), "=r"(r1), "=r"(r2), "=r"(r3) : "r"(addr));
}
__device__ __forceinline__ void ldsm_x4_t(uint32_t addr, uint32_t& r0, uint32_t& r1,
                                          uint32_t& r2, uint32_t& r3) {
    asm volatile("ldmatrix.sync.aligned.m8n8.x4.trans.shared.b16 {%0,%1,%2,%3}, [%4];"
                 : "=r"(r0), "=r"(r1), "=r"(r2), "=r"(r3) : "r"(addr));
}

__device__ __forceinline__ void mma16816(float* d, const uint32_t* a, const uint32_t* b) {
    asm volatile(
        "mma.sync.aligned.m16n8k16.row.col.f32.bf16.bf16.f32 "
        "{%0,%1,%2,%3}, {%4,%5,%6,%7}, {%8,%9}, {%0,%1,%2,%3};"
        : "+f"(d[0]), "+f"(d[1]), "+f"(d[2]), "+f"(d[3])
        : "r"(a[0]), "r"(a[1]), "r"(a[2]), "r"(a[3]), "r"(b[0]), "r"(b[1]));
}

__device__ __forceinline__ void cp_async16(uint32_t dst, const void* src) {
    asm volatile("cp.async.cg.shared.global [%0], [%1], 16;" :: "r"(dst), "l"(src));
}
#define CP_COMMIT() asm volatile("cp.async.commit_group;" ::: "memory")

__device__ __forceinline__ uint32_t pack_bf16x2(float lo_elem, float hi_elem) {
    __nv_bfloat162 t(__float2bfloat16_rn(lo_elem), __float2bfloat16_rn(hi_elem));
    return *(uint32_t*)&t;
}

// ---------------- split fp32 -> (bf16 hi, bf16 lo) ---------------------------
__global__ void split_bf16_kernel(const float* __restrict__ in,
                                  __nv_bfloat16* __restrict__ hi,
                                  __nv_bfloat16* __restrict__ lo, int n4) {
    int i = blockIdx.x * blockDim.x + threadIdx.x;
    if (i >= n4) return;
    float4 v = ((const float4*)in)[i];
    __nv_bfloat16 h0 = __float2bfloat16_rn(v.x);
    __nv_bfloat16 h1 = __float2bfloat16_rn(v.y);
    __nv_bfloat16 h2 = __float2bfloat16_rn(v.z);
    __nv_bfloat16 h3 = __float2bfloat16_rn(v.w);
    __nv_bfloat16 l0 = __float2bfloat16_rn(v.x - __bfloat162float(h0));
    __nv_bfloat16 l1 = __float2bfloat16_rn(v.y - __bfloat162float(h1));
    __nv_bfloat16 l2 = __float2bfloat16_rn(v.z - __bfloat162float(h2));
    __nv_bfloat16 l3 = __float2bfloat16_rn(v.w - __bfloat162float(h3));
    ((__nv_bfloat162*)hi)[2 * i]     = __nv_bfloat162(h0, h1);
    ((__nv_bfloat162*)hi)[2 * i + 1] = __nv_bfloat162(h2, h3);
    ((__nv_bfloat162*)lo)[2 * i]     = __nv_bfloat162(l0, l1);
    ((__nv_bfloat162*)lo)[2 * i + 1] = __nv_bfloat162(l2, l3);
}

// ---------------- split+remap fp32 qkv -> per-head bf16 hi/lo Q,K,V ---------
__global__ void split_qkv_kernel(const float* __restrict__ qkv,
                                 __nv_bfloat16* __restrict__ qh, __nv_bfloat16* __restrict__ ql,
                                 __nv_bfloat16* __restrict__ kh, __nv_bfloat16* __restrict__ kl,
                                 __nv_bfloat16* __restrict__ vh, __nv_bfloat16* __restrict__ vl) {
    int i = blockIdx.x * blockDim.x + threadIdx.x;   // one float4
    if (i >= BT * QKV_N / 4) return;
    int row = i / (QKV_N / 4);
    int c = (i - row * (QKV_N / 4)) * 4;
    int h = c / 192;
    int w = c - h * 192;
    int part = w >> 6;           // 0=q 1=k 2=v
    int d = w & 63;
    int b = row >> 11, t = row & 2047;
    size_t dst = ((size_t)(b * N_HEADS + h) * SEQ + t) * HEAD_DIM + d;
    float4 v = ((const float4*)qkv)[i];
    __nv_bfloat16 h0 = __float2bfloat16_rn(v.x);
    __nv_bfloat16 h1 = __float2bfloat16_rn(v.y);
    __nv_bfloat16 h2 = __float2bfloat16_rn(v.z);
    __nv_bfloat16 h3 = __float2bfloat16_rn(v.w);
    __nv_bfloat16 l0 = __float2bfloat16_rn(v.x - __bfloat162float(h0));
    __nv_bfloat16 l1 = __float2bfloat16_rn(v.y - __bfloat162float(h1));
    __nv_bfloat16 l2 = __float2bfloat16_rn(v.z - __bfloat162float(h2));
    __nv_bfloat16 l3 = __float2bfloat16_rn(v.w - __bfloat162float(h3));
    __nv_bfloat16* H = part == 0 ? qh : (part == 1 ? kh : vh);
    __nv_bfloat16* L = part == 0 ? ql : (part == 1 ? kl : vl);
    ((__nv_bfloat162*)(H + dst))[0] = __nv_bfloat162(h0, h1);
    ((__nv_bfloat162*)(H + dst))[1] = __nv_bfloat162(h2, h3);
    ((__nv_bfloat162*)(L + dst))[0] = __nv_bfloat162(l0, l1);
    ((__nv_bfloat162*)(L + dst))[1] = __nv_bfloat162(l2, l3);
}

// ---------------- HMMA GEMM (unchanged from round 3) -------------------------
#define GEMM_KC 64
#define TILE_B 16384
#define STAGE_B (4 * TILE_B)
#define GEMM_SMEM (2 * STAGE_B)

__device__ __forceinline__ void load_tile_async(uint32_t smem_dst,
                                                const __nv_bfloat16* __restrict__ g,
                                                int base_row, int K, int kc, int tid) {
    #pragma unroll
    for (int i = 0; i < 4; i++) {
        int idx = tid + i * 256;
        int r = idx >> 3;
        int c = (idx & 7) << 4;
        const char* src = (const char*)(g + (size_t)(base_row + r) * K + kc) + c;
        cp_async16(smem_dst + SWZ((uint32_t)(r * 128 + c)), src);
    }
}

__global__ void __launch_bounds__(256, 1)
gemm_tc_kernel(const __nv_bfloat16* __restrict__ Ahi,
               const __nv_bfloat16* __restrict__ Alo,
               const __nv_bfloat16* __restrict__ Bhi,
               const __nv_bfloat16* __restrict__ Blo,
               const float* __restrict__ bias,
               float* __restrict__ C,
               int M, int N, int K) {
    extern __shared__ char smem[];
    const uint32_t sb = smem_to_u32(smem);
    const int tid = threadIdx.x;
    const int wid = tid >> 5;
    const int lane = tid & 31;
    const int warp_m = wid >> 2;
    const int warp_n = wid & 3;
    const int row0 = blockIdx.y * 128;
    const int col0 = blockIdx.x * 128;
    const int NC = K / GEMM_KC;

    float acc[4][4][4];
    #pragma unroll
    for (int mt = 0; mt < 4; mt++)
        #pragma unroll
        for (int nt = 0; nt < 4; nt++)
            acc[mt][nt][0] = acc[mt][nt][1] = acc[mt][nt][2] = acc[mt][nt][3] = 0.f;

    const uint32_t a_row = warp_m * 64 + (lane & 15);
    const uint32_t a_colb = (lane >> 4) << 4;
    const uint32_t b_row = warp_n * 32 + (lane & 7) + ((lane >> 4) & 1) * 8;
    const uint32_t b_colb = ((lane >> 3) & 1) << 4;

    {
        load_tile_async(sb,              Ahi, row0, K, 0, tid);
        load_tile_async(sb + TILE_B,     Alo, row0, K, 0, tid);
        load_tile_async(sb + 2 * TILE_B, Bhi, col0, K, 0, tid);
        load_tile_async(sb + 3 * TILE_B, Blo, col0, K, 0, tid);
        CP_COMMIT();
    }

    for (int c = 0; c < NC; ++c) {
        if (c + 1 < NC) {
            uint32_t sn = sb + ((c + 1) & 1) * STAGE_B;
            int kc = (c + 1) * GEMM_KC;
            load_tile_async(sn,              Ahi, row0, K, kc, tid);
            load_tile_async(sn + TILE_B,     Alo, row0, K, kc, tid);
            load_tile_async(sn + 2 * TILE_B, Bhi, col0, K, kc, tid);
            load_tile_async(sn + 3 * TILE_B, Blo, col0, K, kc, tid);
            CP_COMMIT();
            asm volatile("cp.async.wait_group 1;" ::: "memory");
        } else {
            asm volatile("cp.async.wait_group 0;" ::: "memory");
        }
        __syncthreads();

        const uint32_t s = sb + (c & 1) * STAGE_B;
        #pragma unroll
        for (int ks = 0; ks < 4; ks++) {
            const uint32_t kb = ks * 32;
            uint32_t aH[4][4], aL[4][4], bH[4][2], bL[4][2];
            #pragma unroll
            for (int mt = 0; mt < 4; mt++) {
                uint32_t off = SWZ((a_row + mt * 16) * 128 + kb + a_colb);
                ldsm_x4(s + off,          aH[mt][0], aH[mt][1], aH[mt][2], aH[mt][3]);
                ldsm_x4(s + TILE_B + off, aL[mt][0], aL[mt][1], aL[mt][2], aL[mt][3]);
            }
            #pragma unroll
            for (int np = 0; np < 2; np++) {
                uint32_t off = SWZ((b_row + np * 16) * 128 + kb + b_colb);
                uint32_t r0, r1, r2, r3;
                ldsm_x4(s + 2 * TILE_B + off, r0, r1, r2, r3);
                bH[np * 2][0] = r0; bH[np * 2][1] = r1;
                bH[np * 2 + 1][0] = r2; bH[np * 2 + 1][1] = r3;
                ldsm_x4(s + 3 * TILE_B + off, r0, r1, r2, r3);
                bL[np * 2][0] = r0; bL[np * 2][1] = r1;
                bL[np * 2 + 1][0] = r2; bL[np * 2 + 1][1] = r3;
            }
            #pragma unroll
            for (int mt = 0; mt < 4; mt++)
                #pragma unroll
                for (int nt = 0; nt < 4; nt++) {
                    mma16816(acc[mt][nt], aH[mt], bH[nt]);
                    mma16816(acc[mt][nt], aH[mt], bL[nt]);
                    mma16816(acc[mt][nt], aL[mt], bH[nt]);
                }
        }
        __syncthreads();
    }

    const int er0 = row0 + warp_m * 64 + (lane >> 2);
    const int ec0 = col0 + warp_n * 32 + (lane & 3) * 2;
    #pragma unroll
    for (int mt = 0; mt < 4; mt++) {
        #pragma unroll
        for (int nt = 0; nt < 4; nt++) {
            const int cc = ec0 + nt * 8;
            const float b0 = bias[cc], b1 = bias[cc + 1];
            const int r0 = er0 + mt * 16;
            float2 v0 = make_float2(acc[mt][nt][0] + b0, acc[mt][nt][1] + b1);
            float2 v1 = make_float2(acc[mt][nt][2] + b0, acc[mt][nt][3] + b1);
            *(float2*)(C + (size_t)r0 * N + cc) = v0;
            *(float2*)(C + (size_t)(r0 + 8) * N + cc) = v1;
        }
    }
}

// ---------------- HMMA flash attention ---------------------------------------
// CTA: 128 queries x one (b,h). 8 warps x 16 query rows.
// smem: Qhi,Qlo (16KB each) + 2 stages x (Khi,Klo,Vhi,Vlo) = 160KB.
#define AT_SMEM (160 * 1024)
#define AT_STAGE0 32768
#define AT_STAGE_B 65536

__device__ __forceinline__ void load_head_tile(uint32_t smem_dst,
                                               const __nv_bfloat16* __restrict__ g,
                                               int bh, int t0, int tid) {
    #pragma unroll
    for (int i = 0; i < 4; i++) {
        int idx = tid + i * 256;
        int r = idx >> 3;
        int c = (idx & 7) << 4;
        const char* src = (const char*)(g + ((size_t)bh * SEQ + t0 + r) * HEAD_DIM) + c;
        cp_async16(smem_dst + SWZ((uint32_t)(r * 128 + c)), src);
    }
}

__global__ void __launch_bounds__(256, 1)
attn_tc_kernel(const __nv_bfloat16* __restrict__ qh, const __nv_bfloat16* __restrict__ ql,
               const __nv_bfloat16* __restrict__ kh, const __nv_bfloat16* __restrict__ kl,
               const __nv_bfloat16* __restrict__ vh, const __nv_bfloat16* __restrict__ vl,
               __nv_bfloat16* __restrict__ out_hi, __nv_bfloat16* __restrict__ out_lo) {
    extern __shared__ char smem[];
    const uint32_t sb = smem_to_u32(smem);
    const int tid = threadIdx.x;
    const int wid = tid >> 5;
    const int lane = tid & 31;
    const int bh = blockIdx.y;
    const int q0 = blockIdx.x * 128;
    const float scale = 0.125f;

    // prologue: Q (group 0), K/V stage 0 (group 1)
    load_head_tile(sb,         qh, bh, q0, tid);
    load_head_tile(sb + 16384, ql, bh, q0, tid);
    CP_COMMIT();
    {
        uint32_t s0 = sb + AT_STAGE0;
        load_head_tile(s0,          kh, bh, 0, tid);
        load_head_tile(s0 + 16384,  kl, bh, 0, tid);
        load_head_tile(s0 + 32768,  vh, bh, 0, tid);
        load_head_tile(s0 + 49152,  vl, bh, 0, tid);
        CP_COMMIT();
    }
    asm volatile("cp.async.wait_group 1;" ::: "memory");
    __syncthreads();

    // Q fragments (register resident)
    uint32_t qhi[4][4], qlo[4][4];
    {
        const uint32_t a_row = wid * 16 + (lane & 15);
        const uint32_t a_colb = (lane >> 4) << 4;
        #pragma unroll
        for (int ks = 0; ks < 4; ks++) {
            uint32_t off = SWZ(a_row * 128 + ks * 32 + a_colb);
            ldsm_x4(sb + off,         qhi[ks][0], qhi[ks][1], qhi[ks][2], qhi[ks][3]);
            ldsm_x4(sb + 16384 + off, qlo[ks][0], qlo[ks][1], qlo[ks][2], qlo[ks][3]);
        }
    }

    float m0 = -1e30f, m1 = -1e30f, l0 = 0.f, l1 = 0.f;
    float accO[8][4];
    #pragma unroll
    for (int nt = 0; nt < 8; nt++)
        accO[nt][0] = accO[nt][1] = accO[nt][2] = accO[nt][3] = 0.f;

    const uint32_t kb_row = (lane & 7) + ((lane >> 4) & 1) * 8;   // K b-frag row part
    const uint32_t kb_colb = ((lane >> 3) & 1) << 4;
    const uint32_t vb_row = (lane & 7) + ((lane >> 3) & 1) * 8;   // V trans row part
    const uint32_t vb_colb = ((lane >> 4) & 1) << 4;

    const int NT = SEQ / 128;  // 16
    for (int kt = 0; kt < NT; kt++) {
        if (kt + 1 < NT) {
            uint32_t sn = sb + AT_STAGE0 + ((kt + 1) & 1) * AT_STAGE_B;
            int t0 = (kt + 1) * 128;
            load_head_tile(sn,          kh, bh, t0, tid);
            load_head_tile(sn + 16384,  kl, bh, t0, tid);
            load_head_tile(sn + 32768,  vh, bh, t0, tid);
            load_head_tile(sn + 49152,  vl, bh, t0, tid);
            CP_COMMIT();
            asm volatile("cp.async.wait_group 1;" ::: "memory");
        } else {
            asm volatile("cp.async.wait_group 0;" ::: "memory");
        }
        __syncthreads();

        const uint32_t s = sb + AT_STAGE0 + (kt & 1) * AT_STAGE_B;

        // ---- S = Q @ K^T (split: QhiKhi + QhiKlo + QloKhi) ----
        float accS[16][4];
        #pragma unroll
        for (int nt = 0; nt < 16; nt++)
            accS[nt][0] = accS[nt][1] = accS[nt][2] = accS[nt][3] = 0.f;

        #pragma unroll
        for (int ks = 0; ks < 4; ks++) {
            const uint32_t kb = ks * 32;
            #pragma unroll
            for (int ntp = 0; ntp < 8; ntp++) {
                uint32_t off = SWZ((ntp * 16 + kb_row) * 128 + kb + kb_colb);
                uint32_t h0, h1, h2, h3, u0, u1, u2, u3;
                ldsm_x4(s + off,         h0, h1, h2, h3);
                ldsm_x4(s + 16384 + off, u0, u1, u2, u3);
                uint32_t bh0[2] = {h0, h1}, bh1[2] = {h2, h3};
                uint32_t bl0[2] = {u0, u1}, bl1[2] = {u2, u3};
                mma16816(accS[2 * ntp],     qhi[ks], bh0);
                mma16816(accS[2 * ntp + 1], qhi[ks], bh1);
                mma16816(accS[2 * ntp],     qhi[ks], bl0);
                mma16816(accS[2 * ntp + 1], qhi[ks], bl1);
                mma16816(accS[2 * ntp],     qlo[ks], bh0);
                mma16816(accS[2 * ntp + 1], qlo[ks], bh1);
            }
        }

        // ---- online softmax (each thread: 2 rows x 32 cols) ----
        float tmax0 = -1e30f, tmax1 = -1e30f;
        #pragma unroll
        for (int nt = 0; nt < 16; nt++) {
            accS[nt][0] *= scale; accS[nt][1] *= scale;
            accS[nt][2] *= scale; accS[nt][3] *= scale;
            tmax0 = fmaxf(tmax0, fmaxf(accS[nt][0], accS[nt][1]));
            tmax1 = fmaxf(tmax1, fmaxf(accS[nt][2], accS[nt][3]));
        }
        tmax0 = fmaxf(tmax0, __shfl_xor_sync(0xffffffffu, tmax0, 1));
        tmax0 = fmaxf(tmax0, __shfl_xor_sync(0xffffffffu, tmax0, 2));
        tmax1 = fmaxf(tmax1, __shfl_xor_sync(0xffffffffu, tmax1, 1));
        tmax1 = fmaxf(tmax1, __shfl_xor_sync(0xffffffffu, tmax1, 2));
        float mnew0 = fmaxf(m0, tmax0);
        float mnew1 = fmaxf(m1, tmax1);
        float alpha0 = __expf(m0 - mnew0);
        float alpha1 = __expf(m1 - mnew1);
        float sum0 = 0.f, sum1 = 0.f;
        #pragma unroll
        for (int nt = 0; nt < 16; nt++) {
            accS[nt][0] = __expf(accS[nt][0] - mnew0);
            accS[nt][1] = __expf(accS[nt][1] - mnew0);
            accS[nt][2] = __expf(accS[nt][2] - mnew1);
            accS[nt][3] = __expf(accS[nt][3] - mnew1);
            sum0 += accS[nt][0] + accS[nt][1];
            sum1 += accS[nt][2] + accS[nt][3];
        }
        sum0 += __shfl_xor_sync(0xffffffffu, sum0, 1);
        sum0 += __shfl_xor_sync(0xffffffffu, sum0, 2);
        sum1 += __shfl_xor_sync(0xffffffffu, sum1, 1);
        sum1 += __shfl_xor_sync(0xffffffffu, sum1, 2);
        l0 = l0 * alpha0 + sum0;
        l1 = l1 * alpha1 + sum1;
        m0 = mnew0; m1 = mnew1;
        #pragma unroll
        for (int nt = 0; nt < 8; nt++) {
            accO[nt][0] *= alpha0; accO[nt][1] *= alpha0;
            accO[nt][2] *= alpha1; accO[nt][3] *= alpha1;
        }

        // ---- O += P @ V (split: PhiVhi + PhiVlo + PloVhi) ----
        #pragma unroll
        for (int kc = 0; kc < 8; kc++) {
            // build P a-fragments from accS (c-frag -> a-frag identity)
            float p00 = accS[2 * kc][0],     p01 = accS[2 * kc][1];
            float p02 = accS[2 * kc][2],     p03 = accS[2 * kc][3];
            float p10 = accS[2 * kc + 1][0], p11 = accS[2 * kc + 1][1];
            float p12 = accS[2 * kc + 1][2], p13 = accS[2 * kc + 1][3];
            uint32_t phi[4], plo[4];
            phi[0] = pack_bf16x2(p00, p01);
            phi[1] = pack_bf16x2(p02, p03);
            phi[2] = pack_bf16x2(p10, p11);
            phi[3] = pack_bf16x2(p12, p13);
            {
                __nv_bfloat162 t0v = *(__nv_bfloat162*)&phi[0];
                __nv_bfloat162 t1v = *(__nv_bfloat162*)&phi[1];
                __nv_bfloat162 t2v = *(__nv_bfloat162*)&phi[2];
                __nv_bfloat162 t3v = *(__nv_bfloat162*)&phi[3];
                plo[0] = pack_bf16x2(p00 - __bfloat162float(t0v.x), p01 - __bfloat162float(t0v.y));
                plo[1] = pack_bf16x2(p02 - __bfloat162float(t1v.x), p03 - __bfloat162float(t1v.y));
                plo[2] = pack_bf16x2(p10 - __bfloat162float(t2v.x), p11 - __bfloat162float(t2v.y));
                plo[3] = pack_bf16x2(p12 - __bfloat162float(t3v.x), p13 - __bfloat162float(t3v.y));
            }
            const uint32_t vrow = kc * 16 + vb_row;
            #pragma unroll
            for (int np = 0; np < 4; np++) {
                uint32_t off = SWZ(vrow * 128 + np * 32 + vb_colb);
                uint32_t h0, h1, h2, h3, u0, u1, u2, u3;
                ldsm_x4_t(s + 32768 + off, h0, h1, h2, h3);
                ldsm_x4_t(s + 49152 + off, u0, u1, u2, u3);
                uint32_t bh0[2] = {h0, h1}, bh1[2] = {h2, h3};
                uint32_t bl0[2] = {u0, u1}, bl1[2] = {u2, u3};
                mma16816(accO[2 * np],     phi, bh0);
                mma16816(accO[2 * np + 1], phi, bh1);
                mma16816(accO[2 * np],     phi, bl0);
                mma16816(accO[2 * np + 1], phi, bl1);
                mma16816(accO[2 * np],     plo, bh0);
                mma16816(accO[2 * np + 1], plo, bh1);
            }
        }
        __syncthreads();
    }

    // ---- epilogue: normalize, split to bf16 hi/lo, store [bt][h*64+d] ----
    const float inv0 = 1.0f / l0;
    const float inv1 = 1.0f / l1;
    const int b = bh >> 4, h = bh & 15;
    const int t_row = q0 + wid * 16 + (lane >> 2);
    #pragma unroll
    for (int nt = 0; nt < 8; nt++) {
        const int col = h * HEAD_DIM + nt * 8 + (lane & 3) * 2;
        float v00 = accO[nt][0] * inv0, v01 = accO[nt][1] * inv0;
        float v10 = accO[nt][2] * inv1, v11 = accO[nt][3] * inv1;
        size_t i0 = ((size_t)(b * SEQ + t_row)) * D_MODEL + col;
        size_t i1 = ((size_t)(b * SEQ + t_row + 8)) * D_MODEL + col;
        uint32_t h00 = pack_bf16x2(v00, v01);
        uint32_t h10 = pack_bf16x2(v10, v11);
        __nv_bfloat162 hb0 = *(__nv_bfloat162*)&h00;
        __nv_bfloat162 hb1 = *(__nv_bfloat162*)&h10;
        uint32_t l00 = pack_bf16x2(v00 - __bfloat162float(hb0.x), v01 - __bfloat162float(hb0.y));
        uint32_t l10 = pack_bf16x2(v10 - __bfloat162float(hb1.x), v11 - __bfloat162float(hb1.y));
        *(uint32_t*)(out_hi + i0) = h00;
        *(uint32_t*)(out_lo + i0) = l00;
        *(uint32_t*)(out_hi + i1) = h10;
        *(uint32_t*)(out_lo + i1) = l10;
    }
}

// -----------------------------------------------------------------------------
extern "C" void kernel_launch(void* const* d_in, const int* in_sizes, int n_in,
                              void* d_out, int out_size) {
    const float* x = nullptr;
    const float* Wqkv = nullptr;
    const float* bqkv = nullptr;
    const float* Wo = nullptr;
    const float* bo = nullptr;
    for (int i = 0; i < n_in; i++) {
        int s = in_sizes[i];
        const float* p = (const float*)d_in[i];
        if (s == BT * D_MODEL) x = p;
        else if (s == 3 * D_MODEL * D_MODEL) Wqkv = p;
        else if (s == 3 * D_MODEL) bqkv = p;
        else if (s == D_MODEL * D_MODEL) Wo = p;
        else if (s == D_MODEL) bo = p;
    }

    float* qkv = nullptr;
    __nv_bfloat16 *ahi, *alo, *wqhi, *wqlo, *wohi, *wolo;
    __nv_bfloat16 *qh, *ql, *kh, *kl, *vh, *vl;
    cudaGetSymbolAddress((void**)&qkv, g_qkv);
    cudaGetSymbolAddress((void**)&ahi, g_ahi);
    cudaGetSymbolAddress((void**)&alo, g_alo);
    cudaGetSymbolAddress((void**)&wqhi, g_wqkv_hi);
    cudaGetSymbolAddress((void**)&wqlo, g_wqkv_lo);
    cudaGetSymbolAddress((void**)&wohi, g_wo_hi);
    cudaGetSymbolAddress((void**)&wolo, g_wo_lo);
    cudaGetSymbolAddress((void**)&qh, g_qh);
    cudaGetSymbolAddress((void**)&ql, g_ql);
    cudaGetSymbolAddress((void**)&kh, g_kh);
    cudaGetSymbolAddress((void**)&kl, g_kl);
    cudaGetSymbolAddress((void**)&vh, g_vh);
    cudaGetSymbolAddress((void**)&vl, g_vl);

    cudaFuncSetAttribute(gemm_tc_kernel,
                         cudaFuncAttributeMaxDynamicSharedMemorySize, GEMM_SMEM);
    cudaFuncSetAttribute(attn_tc_kernel,
                         cudaFuncAttributeMaxDynamicSharedMemorySize, AT_SMEM);

    // split inputs to bf16 hi/lo
    {
        int n4 = BT * D_MODEL / 4;
        split_bf16_kernel<<<(n4 + 255) / 256, 256>>>(x, ahi, alo, n4);
        n4 = QKV_N * D_MODEL / 4;
        split_bf16_kernel<<<(n4 + 255) / 256, 256>>>(Wqkv, wqhi, wqlo, n4);
        n4 = D_MODEL * D_MODEL / 4;
        split_bf16_kernel<<<(n4 + 255) / 256, 256>>>(Wo, wohi, wolo, n4);
    }

    // 1) QKV projection (HMMA) -> fp32 qkv
    gemm_tc_kernel<<<dim3(QKV_N / 128, BT / 128), 256, GEMM_SMEM>>>(
        ahi, alo, wqhi, wqlo, bqkv, qkv, BT, QKV_N, D_MODEL);

    // 2) split + remap to per-head bf16 hi/lo
    {
        int n4 = BT * QKV_N / 4;
        split_qkv_kernel<<<(n4 + 255) / 256, 256>>>(qkv, qh, ql, kh, kl, vh, vl);
    }

    // 3) attention (HMMA flash) -> writes ahi/alo directly
    attn_tc_kernel<<<dim3(SEQ / 128, BATCH * N_HEADS), 256, AT_SMEM>>>(
        qh, ql, kh, kl, vh, vl, ahi, alo);

    // 4) output projection (HMMA)
    gemm_tc_kernel<<<dim3(D_MODEL / 128, BT / 128), 256, GEMM_SMEM>>>(
        ahi, alo, wohi, wolo, bo, (float*)d_out, BT, D_MODEL, D_MODEL);
}